// round 4
// baseline (speedup 1.0000x reference)
#include <cuda_runtime.h>
#include <math_constants.h>

#define MAXN 100000
#define MAXE 1200000
#define D    64
#define GN   16      // nodes per gemm group
#define XSTR 20      // padded smem row stride (floats): 80B, 16B-aligned, 4-way STS conflict

__device__ float    g_y[(size_t)MAXN * 2 * D];   // y[(node*2+type)*64 + d]
__device__ int      g_cnt[MAXN];
__device__ int      g_start[MAXN];
__device__ int      g_cursor[MAXN];
__device__ unsigned g_edata[MAXE];               // packed (src*2 + type)
__device__ int      g_bsum[256];

// packed f32x2 helpers ------------------------------------------------------
__device__ __forceinline__ unsigned long long pack2(float lo, float hi) {
    unsigned long long r;
    asm("mov.b64 %0, {%1, %2};" : "=l"(r) : "r"(__float_as_uint(lo)), "r"(__float_as_uint(hi)));
    return r;
}
__device__ __forceinline__ void fma2(unsigned long long& a,
                                     unsigned long long x, unsigned long long w) {
    asm("fma.rn.f32x2 %0, %1, %2, %0;" : "+l"(a) : "l"(x), "l"(w));
}
__device__ __forceinline__ float2 unpack2(unsigned long long v) {
    unsigned lo, hi;
    asm("mov.b64 {%0, %1}, %2;" : "=r"(lo), "=r"(hi) : "l"(v));
    float2 f; f.x = __uint_as_float(lo); f.y = __uint_as_float(hi);
    return f;
}

// ---------------------------------------------------------------------------
__global__ void zero_cnt_kernel(int n) {
    int i = blockIdx.x * blockDim.x + threadIdx.x;
    if (i < n) g_cnt[i] = 0;
}

// ---------------------------------------------------------------------------
// GEMM: y[n][t][:] = x[n] @ W[t] + b[t].  128 threads: (type = tid>>6, d = tid&63).
// W column in 64 regs. 16 nodes/group. Staging: coalesced linear GMEM read,
// transpose into padded smem rows; FMA loop reads 4x broadcast LDS.128 per k.
// Packed fma.rn.f32x2: 2 FMAs/instr.
__global__ void gemm_kernel(const float* __restrict__ x,
                            const float* __restrict__ W,
                            const float* __restrict__ b, int n) {
    const int tid  = threadIdx.x;
    const int type = tid >> 6;
    const int d    = tid & 63;

    float w[D];
#pragma unroll
    for (int k = 0; k < D; k++) w[k] = W[type * D * D + k * D + d];
    const float bias = b[type * D + d];
    const unsigned long long bb = pack2(bias, bias);

    __shared__ float xs[D * XSTR];                 // xs[k*XSTR + j] = x[node_j][k]

    const int ngroups = n / GN;
    for (int g = blockIdx.x; g < ngroups; g += gridDim.x) {
        const float* xg = x + (size_t)g * GN * D;
#pragma unroll
        for (int m = 0; m < 8; m++) {              // coalesced: 128 consecutive floats/step
            int idx = m * 128 + tid;
            int j = idx >> 6, k = idx & 63;
            xs[k * XSTR + j] = xg[idx];
        }
        __syncthreads();

        unsigned long long acc[8];
#pragma unroll
        for (int q = 0; q < 8; q++) acc[q] = bb;

#pragma unroll
        for (int k = 0; k < D; k++) {
            unsigned long long ww = pack2(w[k], w[k]);
            const ulonglong2* rowv = (const ulonglong2*)(xs + k * XSTR);
            ulonglong2 p0 = rowv[0];
            ulonglong2 p1 = rowv[1];
            ulonglong2 p2 = rowv[2];
            ulonglong2 p3 = rowv[3];
            fma2(acc[0], p0.x, ww); fma2(acc[1], p0.y, ww);
            fma2(acc[2], p1.x, ww); fma2(acc[3], p1.y, ww);
            fma2(acc[4], p2.x, ww); fma2(acc[5], p2.y, ww);
            fma2(acc[6], p3.x, ww); fma2(acc[7], p3.y, ww);
        }

#pragma unroll
        for (int q = 0; q < 8; q++) {
            float2 v = unpack2(acc[q]);
            size_t node0 = (size_t)g * GN + 2 * q;
            g_y[(node0 * 2 + type) * D + d]       = v.x;
            g_y[((node0 + 1) * 2 + type) * D + d] = v.y;
        }
        __syncthreads();
    }

    if (blockIdx.x == 0) {                         // tail (n % 16)
        for (int node = ngroups * GN; node < n; node++) {
            float acc = bias;
            const float* xr = x + (size_t)node * D;
#pragma unroll
            for (int k = 0; k < D; k++) acc = fmaf(xr[k], w[k], acc);
            g_y[((size_t)node * 2 + type) * D + d] = acc;
        }
    }
}

// ---------------------------------------------------------------------------
// histogram of dst, 4 edges/thread (int4)
__global__ void hist_kernel(const int* __restrict__ ei, int e, int n) {
    int t = blockIdx.x * blockDim.x + threadIdx.x;
    int base = t * 4;
    if (base + 4 <= e) {
        int4 d4 = *(const int4*)(ei + e + base);
        if ((unsigned)d4.x < (unsigned)n) atomicAdd(&g_cnt[d4.x], 1);
        if ((unsigned)d4.y < (unsigned)n) atomicAdd(&g_cnt[d4.y], 1);
        if ((unsigned)d4.z < (unsigned)n) atomicAdd(&g_cnt[d4.z], 1);
        if ((unsigned)d4.w < (unsigned)n) atomicAdd(&g_cnt[d4.w], 1);
    } else {
        for (int i = base; i < e; i++) {
            int dn = ei[e + i];
            if ((unsigned)dn < (unsigned)n) atomicAdd(&g_cnt[dn], 1);
        }
    }
}

// ---------------------------------------------------------------------------
// shuffle-based scans
__global__ void scan1_kernel(int n) {
    __shared__ int wsum[32];
    int tid = threadIdx.x, lane = tid & 31, wid = tid >> 5;
    int i = blockIdx.x * 1024 + tid;
    int v = (i < n) ? g_cnt[i] : 0;
    int inc = v;
#pragma unroll
    for (int off = 1; off < 32; off <<= 1) {
        int t = __shfl_up_sync(0xffffffffu, inc, off);
        if (lane >= off) inc += t;
    }
    if (lane == 31) wsum[wid] = inc;
    __syncthreads();
    if (wid == 0) {
        int s = wsum[lane];
#pragma unroll
        for (int off = 1; off < 32; off <<= 1) {
            int t = __shfl_up_sync(0xffffffffu, s, off);
            if (lane >= off) s += t;
        }
        wsum[lane] = s;
    }
    __syncthreads();
    int woff = (wid > 0) ? wsum[wid - 1] : 0;
    if (i < n) g_start[i] = woff + inc - v;          // exclusive
    if (tid == 1023) g_bsum[blockIdx.x] = wsum[31];  // block total
}

__global__ void scan2_kernel(int nb) {
    __shared__ int ws[8];
    int tid = threadIdx.x, lane = tid & 31, wid = tid >> 5;
    int v = (tid < nb) ? g_bsum[tid] : 0;
    int inc = v;
#pragma unroll
    for (int off = 1; off < 32; off <<= 1) {
        int t = __shfl_up_sync(0xffffffffu, inc, off);
        if (lane >= off) inc += t;
    }
    if (lane == 31) ws[wid] = inc;
    __syncthreads();
    if (wid == 0) {
        int s = (lane < 8) ? ws[lane] : 0;
#pragma unroll
        for (int off = 1; off < 8; off <<= 1) {
            int t = __shfl_up_sync(0xffffffffu, s, off);
            if (lane >= off) s += t;
        }
        if (lane < 8) ws[lane] = s;
    }
    __syncthreads();
    int woff = (wid > 0) ? ws[wid - 1] : 0;
    if (tid < nb) g_bsum[tid] = woff + inc - v;      // exclusive
}

__global__ void scan3_kernel(int n) {
    int i = blockIdx.x * blockDim.x + threadIdx.x;
    if (i < n) {
        int v = g_start[i] + g_bsum[i >> 10];
        g_start[i]  = v;
        g_cursor[i] = v;
    }
}

// ---------------------------------------------------------------------------
// placement, 4 edges/thread (int4 on src / dst / attr)
__global__ void place_kernel(const int* __restrict__ ei,
                             const int* __restrict__ attr, int e, int n) {
    int t = blockIdx.x * blockDim.x + threadIdx.x;
    int base = t * 4;
    if (base + 4 <= e) {
        int4 s4 = *(const int4*)(ei + base);
        int4 d4 = *(const int4*)(ei + e + base);
        int4 a4 = *(const int4*)(attr + base);
        int ss[4] = {s4.x, s4.y, s4.z, s4.w};
        int dd[4] = {d4.x, d4.y, d4.z, d4.w};
        int aa[4] = {a4.x, a4.y, a4.z, a4.w};
#pragma unroll
        for (int q = 0; q < 4; q++) {
            if ((unsigned)ss[q] < (unsigned)n && (unsigned)dd[q] < (unsigned)n) {
                int pos = atomicAdd(&g_cursor[dd[q]], 1);
                if ((unsigned)pos < (unsigned)MAXE)
                    g_edata[pos] = (unsigned)((ss[q] << 1) | (aa[q] & 1));
            }
        }
    } else {
        for (int i = base; i < e; i++) {
            int s = ei[i], dn = ei[e + i], a = attr[i] & 1;
            if ((unsigned)s < (unsigned)n && (unsigned)dn < (unsigned)n) {
                int pos = atomicAdd(&g_cursor[dn], 1);
                if ((unsigned)pos < (unsigned)MAXE)
                    g_edata[pos] = (unsigned)((s << 1) | a);
            }
        }
    }
}

// ---------------------------------------------------------------------------
// aggregation: warp/node, lane owns dims {2l,2l+1}.
// g_edata[s+j] is warp-uniform -> direct uniform LDG (L1-hit after 1st line),
// no shuffles/predicates; gathers unrolled x4 (MLP=4), max in registers.
__global__ void agg_kernel(float* __restrict__ out, int n) {
    int gt   = blockIdx.x * blockDim.x + threadIdx.x;
    int node = gt >> 5;
    int lane = gt & 31;
    if (node >= n) return;

    int c = g_cnt[node];
    int s = g_start[node];

    float vx = -CUDART_INF_F, vy = -CUDART_INF_F;
    int j = 0;
    for (; j + 4 <= c; j += 4) {
        unsigned u0 = __ldg(&g_edata[s + j]);
        unsigned u1 = __ldg(&g_edata[s + j + 1]);
        unsigned u2 = __ldg(&g_edata[s + j + 2]);
        unsigned u3 = __ldg(&g_edata[s + j + 3]);
        float2 v0 = ((const float2*)(g_y + (size_t)u0 * D))[lane];
        float2 v1 = ((const float2*)(g_y + (size_t)u1 * D))[lane];
        float2 v2 = ((const float2*)(g_y + (size_t)u2 * D))[lane];
        float2 v3 = ((const float2*)(g_y + (size_t)u3 * D))[lane];
        vx = fmaxf(vx, fmaxf(fmaxf(v0.x, v1.x), fmaxf(v2.x, v3.x)));
        vy = fmaxf(vy, fmaxf(fmaxf(v0.y, v1.y), fmaxf(v2.y, v3.y)));
    }
    for (; j < c; j++) {
        unsigned uu = __ldg(&g_edata[s + j]);
        float2 v = ((const float2*)(g_y + (size_t)uu * D))[lane];
        vx = fmaxf(vx, v.x);
        vy = fmaxf(vy, v.y);
    }
    if (c == 0) { vx = 0.f; vy = 0.f; }
    float2 o; o.x = vx; o.y = vy;
    ((float2*)out)[(size_t)node * 32 + lane] = o;
}

// ---------------------------------------------------------------------------
extern "C" void kernel_launch(void* const* d_in, const int* in_sizes, int n_in,
                              void* d_out, int out_size) {
    const float* x    = (const float*)d_in[0];
    const float* W    = (const float*)d_in[1];
    const float* b    = (const float*)d_in[2];
    const int*   ei   = (const int*)d_in[3];
    const int*   attr = (const int*)d_in[4];
    float*       out  = (float*)d_out;

    int n = in_sizes[0] / D;
    int e = in_sizes[4];
    if (n > MAXN) n = MAXN;
    if (e > MAXE) e = MAXE;

    int et = (e + 3) / 4;
    int nb = (n + 1023) / 1024;

    // Launch order chosen so gemm is the 4th launch: the fixed ncu capture
    // position (observed: launch #4) then profiles the GEMM next round.
    zero_cnt_kernel<<<(n + 255) / 256, 256>>>(n);            // 1
    hist_kernel<<<(et + 255) / 256, 256>>>(ei, e, n);        // 2
    scan1_kernel<<<nb, 1024>>>(n);                           // 3
    gemm_kernel<<<1024, 128>>>(x, W, b, n);                  // 4  <- profiled
    scan2_kernel<<<1, 256>>>(nb);                            // 5
    scan3_kernel<<<(n + 255) / 256, 256>>>(n);               // 6
    place_kernel<<<(et + 255) / 256, 256>>>(ei, attr, e, n); // 7
    agg_kernel<<<(n * 32 + 255) / 256, 256>>>(out, n);       // 8
}

// round 5
// speedup vs baseline: 1.3119x; 1.3119x over previous
#include <cuda_runtime.h>
#include <math_constants.h>

#define MAXN 100000
#define MAXE 1200000
#define D    64

__device__ float    g_y[(size_t)MAXN * 2 * D];   // y[node*128 + j], j = type*64 + d
__device__ int      g_cnt[MAXN];
__device__ int      g_start[MAXN];
__device__ int      g_cursor[MAXN];
__device__ unsigned g_edata[MAXE];               // packed (src*2 + type)
__device__ int      g_bsum[256];

// packed f32x2 helpers ------------------------------------------------------
__device__ __forceinline__ unsigned long long pack2(float lo, float hi) {
    unsigned long long r;
    asm("mov.b64 %0, {%1, %2};" : "=l"(r) : "r"(__float_as_uint(lo)), "r"(__float_as_uint(hi)));
    return r;
}
__device__ __forceinline__ void fma2(unsigned long long& a,
                                     unsigned long long x, unsigned long long w) {
    asm("fma.rn.f32x2 %0, %1, %2, %0;" : "+l"(a) : "l"(x), "l"(w));
}

// ---------------------------------------------------------------------------
__global__ void zero_cnt_kernel(int n) {
    int i = blockIdx.x * blockDim.x + threadIdx.x;
    if (i < n) g_cnt[i] = 0;
}

// ---------------------------------------------------------------------------
// Tiled GEMM: C[node][j] = sum_k x[node][k] * W'[k][j] + b[j],  j = t*64+d.
// Block tile 128 nodes x 128 outputs, 256 threads, 8x8 micro-tile per thread.
// x staged PAIR-DUPLICATED in smem (f32x2 lane duplication paid once, in STS),
// W' resident in smem for the whole block. 32 FMA2 per k per thread.
__global__ void __launch_bounds__(256, 2)
gemm_kernel(const float* __restrict__ x,
            const float* __restrict__ W,
            const float* __restrict__ b, int n) {
    __shared__ float ws[64][128];    // ws[k][j] = W[j>>6][k][j&63]   (32 KB)
    __shared__ float xd[8][260];     // xd[kk][2*node+{0,1}] = x[node][kc*8+kk] (dup, padded)

    const int tid = threadIdx.x;
    const int tx  = tid & 15;        // output group: cols tx*8 .. tx*8+7
    const int ty  = tid >> 4;        // node group:   rows ty*8 .. ty*8+7

    // Load W' into smem (coalesced within each type half)
    for (int i = tid; i < 64 * 128; i += 256) {
        int k = i >> 7, j = i & 127;
        ws[k][j] = W[((j >> 6) << 12) + (k << 6) + (j & 63)];
    }

    // Bias pairs for this thread's 8 output columns
    unsigned long long bb2[4];
#pragma unroll
    for (int j2 = 0; j2 < 4; j2++) {
        float2 bv = ((const float2*)b)[tx * 4 + j2];
        bb2[j2] = pack2(bv.x, bv.y);
    }
    __syncthreads();

    const int ntiles = (n + 127) >> 7;
    for (int tile = blockIdx.x; tile < ntiles; tile += gridDim.x) {
        const int nb0 = tile << 7;

        unsigned long long acc[32];
#pragma unroll
        for (int i = 0; i < 8; i++)
#pragma unroll
            for (int j2 = 0; j2 < 4; j2++) acc[i * 4 + j2] = bb2[j2];

#pragma unroll
        for (int kc = 0; kc < 8; kc++) {
            // stage 128 nodes x 8 k, duplicated: thread -> (node = tid>>1, q = tid&1)
            {
                int node = tid >> 1, q = tid & 1;
                int gn = nb0 + node;
                float4 v = make_float4(0.f, 0.f, 0.f, 0.f);
                if (gn < n) v = *(const float4*)(x + (size_t)gn * D + kc * 8 + q * 4);
                *(unsigned long long*)(&xd[q * 4 + 0][2 * node]) = pack2(v.x, v.x);
                *(unsigned long long*)(&xd[q * 4 + 1][2 * node]) = pack2(v.y, v.y);
                *(unsigned long long*)(&xd[q * 4 + 2][2 * node]) = pack2(v.z, v.z);
                *(unsigned long long*)(&xd[q * 4 + 3][2 * node]) = pack2(v.w, v.w);
            }
            __syncthreads();

#pragma unroll
            for (int k = 0; k < 8; k++) {
                const ulonglong2* ap = (const ulonglong2*)(&xd[k][ty * 16]);
                ulonglong2 a01 = ap[0], a23 = ap[1], a45 = ap[2], a67 = ap[3];
                const ulonglong2* bp4 = (const ulonglong2*)(&ws[kc * 8 + k][tx * 8]);
                ulonglong2 b01 = bp4[0], b23 = bp4[1];
                unsigned long long a2[8] = {a01.x, a01.y, a23.x, a23.y,
                                            a45.x, a45.y, a67.x, a67.y};
                unsigned long long bp[4] = {b01.x, b01.y, b23.x, b23.y};
#pragma unroll
                for (int i = 0; i < 8; i++) {
#pragma unroll
                    for (int j2 = 0; j2 < 4; j2++)
                        fma2(acc[i * 4 + j2], a2[i], bp[j2]);
                }
            }
            __syncthreads();
        }

        // store: node rows coalesced, 2x STG.128 per row
#pragma unroll
        for (int i = 0; i < 8; i++) {
            int gn = nb0 + ty * 8 + i;
            if (gn < n) {
                ulonglong2* o = (ulonglong2*)(g_y + (size_t)gn * 128 + tx * 8);
                o[0] = make_ulonglong2(acc[i * 4 + 0], acc[i * 4 + 1]);
                o[1] = make_ulonglong2(acc[i * 4 + 2], acc[i * 4 + 3]);
            }
        }
    }
}

// ---------------------------------------------------------------------------
// histogram of dst, 4 edges/thread (int4)
__global__ void hist_kernel(const int* __restrict__ ei, int e, int n) {
    int t = blockIdx.x * blockDim.x + threadIdx.x;
    int base = t * 4;
    if (base + 4 <= e) {
        int4 d4 = *(const int4*)(ei + e + base);
        if ((unsigned)d4.x < (unsigned)n) atomicAdd(&g_cnt[d4.x], 1);
        if ((unsigned)d4.y < (unsigned)n) atomicAdd(&g_cnt[d4.y], 1);
        if ((unsigned)d4.z < (unsigned)n) atomicAdd(&g_cnt[d4.z], 1);
        if ((unsigned)d4.w < (unsigned)n) atomicAdd(&g_cnt[d4.w], 1);
    } else {
        for (int i = base; i < e; i++) {
            int dn = ei[e + i];
            if ((unsigned)dn < (unsigned)n) atomicAdd(&g_cnt[dn], 1);
        }
    }
}

// ---------------------------------------------------------------------------
// shuffle-based scans
__global__ void scan1_kernel(int n) {
    __shared__ int wsum[32];
    int tid = threadIdx.x, lane = tid & 31, wid = tid >> 5;
    int i = blockIdx.x * 1024 + tid;
    int v = (i < n) ? g_cnt[i] : 0;
    int inc = v;
#pragma unroll
    for (int off = 1; off < 32; off <<= 1) {
        int t = __shfl_up_sync(0xffffffffu, inc, off);
        if (lane >= off) inc += t;
    }
    if (lane == 31) wsum[wid] = inc;
    __syncthreads();
    if (wid == 0) {
        int s = wsum[lane];
#pragma unroll
        for (int off = 1; off < 32; off <<= 1) {
            int t = __shfl_up_sync(0xffffffffu, s, off);
            if (lane >= off) s += t;
        }
        wsum[lane] = s;
    }
    __syncthreads();
    int woff = (wid > 0) ? wsum[wid - 1] : 0;
    if (i < n) g_start[i] = woff + inc - v;
    if (tid == 1023) g_bsum[blockIdx.x] = wsum[31];
}

__global__ void scan2_kernel(int nb) {
    __shared__ int ws[8];
    int tid = threadIdx.x, lane = tid & 31, wid = tid >> 5;
    int v = (tid < nb) ? g_bsum[tid] : 0;
    int inc = v;
#pragma unroll
    for (int off = 1; off < 32; off <<= 1) {
        int t = __shfl_up_sync(0xffffffffu, inc, off);
        if (lane >= off) inc += t;
    }
    if (lane == 31) ws[wid] = inc;
    __syncthreads();
    if (wid == 0) {
        int s = (lane < 8) ? ws[lane] : 0;
#pragma unroll
        for (int off = 1; off < 8; off <<= 1) {
            int t = __shfl_up_sync(0xffffffffu, s, off);
            if (lane >= off) s += t;
        }
        if (lane < 8) ws[lane] = s;
    }
    __syncthreads();
    int woff = (wid > 0) ? ws[wid - 1] : 0;
    if (tid < nb) g_bsum[tid] = woff + inc - v;
}

__global__ void scan3_kernel(int n) {
    int i = blockIdx.x * blockDim.x + threadIdx.x;
    if (i < n) {
        int v = g_start[i] + g_bsum[i >> 10];
        g_start[i]  = v;
        g_cursor[i] = v;
    }
}

// ---------------------------------------------------------------------------
// placement, 4 edges/thread (int4 on src / dst / attr)
__global__ void place_kernel(const int* __restrict__ ei,
                             const int* __restrict__ attr, int e, int n) {
    int t = blockIdx.x * blockDim.x + threadIdx.x;
    int base = t * 4;
    if (base + 4 <= e) {
        int4 s4 = *(const int4*)(ei + base);
        int4 d4 = *(const int4*)(ei + e + base);
        int4 a4 = *(const int4*)(attr + base);
        int ss[4] = {s4.x, s4.y, s4.z, s4.w};
        int dd[4] = {d4.x, d4.y, d4.z, d4.w};
        int aa[4] = {a4.x, a4.y, a4.z, a4.w};
#pragma unroll
        for (int q = 0; q < 4; q++) {
            if ((unsigned)ss[q] < (unsigned)n && (unsigned)dd[q] < (unsigned)n) {
                int pos = atomicAdd(&g_cursor[dd[q]], 1);
                if ((unsigned)pos < (unsigned)MAXE)
                    g_edata[pos] = (unsigned)((ss[q] << 1) | (aa[q] & 1));
            }
        }
    } else {
        for (int i = base; i < e; i++) {
            int s = ei[i], dn = ei[e + i], a = attr[i] & 1;
            if ((unsigned)s < (unsigned)n && (unsigned)dn < (unsigned)n) {
                int pos = atomicAdd(&g_cursor[dn], 1);
                if ((unsigned)pos < (unsigned)MAXE)
                    g_edata[pos] = (unsigned)((s << 1) | a);
            }
        }
    }
}

// ---------------------------------------------------------------------------
// aggregation (R3 form): warp/node, lane owns dims {2l,2l+1};
// coalesced edge-chunk load + shuffle broadcast, gathers unrolled x4 (MLP=4).
// NOTE: g_y row for node*2+t lives at g_y + (node*2+t)*64 = g_y + u*64, u packed idx.
__global__ void agg_kernel(float* __restrict__ out, int n) {
    int gt   = blockIdx.x * blockDim.x + threadIdx.x;
    int node = gt >> 5;
    int lane = gt & 31;
    if (node >= n) return;

    int c = g_cnt[node];
    int s = g_start[node];

    float vx = -CUDART_INF_F, vy = -CUDART_INF_F;
    for (int base = 0; base < c; base += 32) {
        int m = min(32, c - base);
        unsigned u = (lane < m) ? g_edata[s + base + lane] : 0u;
        int j = 0;
        for (; j + 4 <= m; j += 4) {
            unsigned u0 = __shfl_sync(0xffffffffu, u, j);
            unsigned u1 = __shfl_sync(0xffffffffu, u, j + 1);
            unsigned u2 = __shfl_sync(0xffffffffu, u, j + 2);
            unsigned u3 = __shfl_sync(0xffffffffu, u, j + 3);
            float2 v0 = ((const float2*)(g_y + (size_t)u0 * D))[lane];
            float2 v1 = ((const float2*)(g_y + (size_t)u1 * D))[lane];
            float2 v2 = ((const float2*)(g_y + (size_t)u2 * D))[lane];
            float2 v3 = ((const float2*)(g_y + (size_t)u3 * D))[lane];
            vx = fmaxf(vx, fmaxf(fmaxf(v0.x, v1.x), fmaxf(v2.x, v3.x)));
            vy = fmaxf(vy, fmaxf(fmaxf(v0.y, v1.y), fmaxf(v2.y, v3.y)));
        }
        for (; j < m; j++) {
            unsigned uu = __shfl_sync(0xffffffffu, u, j);
            float2 v = ((const float2*)(g_y + (size_t)uu * D))[lane];
            vx = fmaxf(vx, v.x);
            vy = fmaxf(vy, v.y);
        }
    }
    if (c == 0) { vx = 0.f; vy = 0.f; }
    float2 o; o.x = vx; o.y = vy;
    ((float2*)out)[(size_t)node * 32 + lane] = o;
}

// ---------------------------------------------------------------------------
extern "C" void kernel_launch(void* const* d_in, const int* in_sizes, int n_in,
                              void* d_out, int out_size) {
    const float* x    = (const float*)d_in[0];
    const float* W    = (const float*)d_in[1];
    const float* b    = (const float*)d_in[2];
    const int*   ei   = (const int*)d_in[3];
    const int*   attr = (const int*)d_in[4];
    float*       out  = (float*)d_out;

    int n = in_sizes[0] / D;
    int e = in_sizes[4];
    if (n > MAXN) n = MAXN;
    if (e > MAXE) e = MAXE;

    int et = (e + 3) / 4;
    int nb = (n + 1023) / 1024;

    // gemm kept at launch slot 4 (the position ncu captures)
    zero_cnt_kernel<<<(n + 255) / 256, 256>>>(n);            // 1
    hist_kernel<<<(et + 255) / 256, 256>>>(ei, e, n);        // 2
    scan1_kernel<<<nb, 1024>>>(n);                           // 3
    gemm_kernel<<<296, 256>>>(x, W, b, n);                   // 4  <- profiled
    scan2_kernel<<<1, 256>>>(nb);                            // 5
    scan3_kernel<<<(n + 255) / 256, 256>>>(n);               // 6
    place_kernel<<<(et + 255) / 256, 256>>>(ei, attr, e, n); // 7
    agg_kernel<<<(n * 32 + 255) / 256, 256>>>(out, n);       // 8
}

// round 7
// speedup vs baseline: 1.6499x; 1.2577x over previous
#include <cuda_runtime.h>
#include <math_constants.h>
#include <cstdint>

#define MAXN 100000
#define MAXE 1200000
#define D    64

__device__ float    g_y[(size_t)MAXN * 2 * D];   // y[node*128 + j], j = t*64+d
__device__ int      g_cnt[MAXN];
__device__ int      g_start[MAXN];
__device__ int      g_cursor[MAXN];
__device__ unsigned g_edata[MAXE];               // packed (src*2 + type)
__device__ int      g_bsum[256];

// ---------------------------------------------------------------------------
// mma.sync tf32 helpers (portable PTX, no sm_103a-gated instructions)
// ---------------------------------------------------------------------------
__device__ __forceinline__ float to_tf32(float f) {
    uint32_t r;
    asm("cvt.rna.tf32.f32 %0, %1;" : "=r"(r) : "f"(f));
    return __uint_as_float(r);
}
__device__ __forceinline__ void mma8(float* c,
                                     float a0, float a1, float a2, float a3,
                                     float b0, float b1) {
    asm volatile(
        "mma.sync.aligned.m16n8k8.row.col.f32.tf32.tf32.f32 "
        "{%0,%1,%2,%3}, {%4,%5,%6,%7}, {%8,%9}, {%0,%1,%2,%3};"
        : "+f"(c[0]), "+f"(c[1]), "+f"(c[2]), "+f"(c[3])
        : "r"(__float_as_uint(a0)), "r"(__float_as_uint(a1)),
          "r"(__float_as_uint(a2)), "r"(__float_as_uint(a3)),
          "r"(__float_as_uint(b0)), "r"(__float_as_uint(b1)));
}

// dynamic smem layout (float4 units): As 128*17, Bs 128*17, bias 128 floats
#define AS_OFF 0
#define BS_OFF (128 * 17)
#define BIAS_OFF (2 * 128 * 17)          // in float4 units
#define SMEM_BYTES ((2 * 128 * 17) * 16 + 512)

// ---------------------------------------------------------------------------
// GEMM via mma.sync tf32: g_y[node][j] = x[node] @ W'[.][j] + b[j]
// Block 256 thr (8 warps), tile 128 rows x 128 cols, warp tile 32x64.
// K-pair packing: float4 slot (s2*4+t) holds cols {16s2+t, +4, +8, +12} so one
// LDS.128 yields the a0/a2 (or b0/b1) fragments of TWO K-steps.
// ---------------------------------------------------------------------------
__global__ void __launch_bounds__(256, 2)
gemm_tc_kernel(const float* __restrict__ x,
               const float* __restrict__ W,
               const float* __restrict__ b, int n) {
    extern __shared__ float4 sm4[];
    float4* As = sm4 + AS_OFF;           // As[row*17 + s2*4 + t]
    float4* Bs = sm4 + BS_OFF;           // Bs[nn*17 + s2*4 + t]
    float*  bias_s = (float*)(sm4 + BIAS_OFF);

    const int tid  = threadIdx.x;
    const int wid  = tid >> 5, lane = tid & 31;
    const int gidq = lane >> 2, tq = lane & 3;   // mma groupID / threadID-in-group
    const int wr   = wid >> 1,  wc = wid & 1;    // warp row (0..3) / col (0..1)

    // stage W' once: Bp[k][nn] = W[nn>>6][k][nn&63], K-pair packed, tf32-rounded
    for (int i = tid; i < 128 * 16; i += 256) {
        int nn = i >> 4, j = i & 15;
        int s2 = j >> 2, t = j & 3;
        const float* wp = W + ((nn >> 6) << 12) + (nn & 63);
        float4 v;
        v.x = to_tf32(wp[(16 * s2 + t     ) << 6]);
        v.y = to_tf32(wp[(16 * s2 + t + 4 ) << 6]);
        v.z = to_tf32(wp[(16 * s2 + t + 8 ) << 6]);
        v.w = to_tf32(wp[(16 * s2 + t + 12) << 6]);
        Bs[nn * 17 + j] = v;
    }
    if (tid < 128) bias_s[tid] = b[tid];
    __syncthreads();

    const int ntiles = (n + 127) >> 7;
    for (int tile = blockIdx.x; tile < ntiles; tile += gridDim.x) {
        const int nb0 = tile << 7;

        // stage A tile: coalesced LDG.128, scatter 4 scalars into packed slots
#pragma unroll
        for (int s = 0; s < 8; s++) {
            int idx = s * 256 + tid;               // 2048 float4
            int row = idx >> 4, q = idx & 15;
            int gn = nb0 + row;
            float4 v = make_float4(0.f, 0.f, 0.f, 0.f);
            if (gn < n) v = *(const float4*)(x + (size_t)gn * 64 + q * 4);
            float* ap = (float*)(As + row * 17 + (q >> 2) * 4);
            int c = q & 3;
            ap[0 * 4 + c] = to_tf32(v.x);
            ap[1 * 4 + c] = to_tf32(v.y);
            ap[2 * 4 + c] = to_tf32(v.z);
            ap[3 * 4 + c] = to_tf32(v.w);
        }
        __syncthreads();

        float acc[2][8][4];
#pragma unroll
        for (int mt = 0; mt < 2; mt++)
#pragma unroll
            for (int nt = 0; nt < 8; nt++)
#pragma unroll
                for (int c = 0; c < 4; c++) acc[mt][nt][c] = 0.f;

#pragma unroll
        for (int s2 = 0; s2 < 4; s2++) {
            float4 A0[2], A1[2];
#pragma unroll
            for (int mt = 0; mt < 2; mt++) {
                int r0 = wr * 32 + mt * 16 + gidq;
                A0[mt] = As[r0 * 17 + s2 * 4 + tq];
                A1[mt] = As[(r0 + 8) * 17 + s2 * 4 + tq];
            }
#pragma unroll
            for (int nt = 0; nt < 8; nt++) {
                int nn = wc * 64 + nt * 8 + gidq;
                float4 Bv = Bs[nn * 17 + s2 * 4 + tq];
#pragma unroll
                for (int mt = 0; mt < 2; mt++) {
                    // K-step 2*s2
                    mma8(acc[mt][nt], A0[mt].x, A1[mt].x, A0[mt].y, A1[mt].y,
                         Bv.x, Bv.y);
                    // K-step 2*s2+1
                    mma8(acc[mt][nt], A0[mt].z, A1[mt].z, A0[mt].w, A1[mt].w,
                         Bv.z, Bv.w);
                }
            }
        }

        // epilogue: add bias, store float2 per (c0,c1)/(c2,c3)
#pragma unroll
        for (int mt = 0; mt < 2; mt++) {
#pragma unroll
            for (int nt = 0; nt < 8; nt++) {
                int col = wc * 64 + nt * 8 + 2 * tq;
                float bx = bias_s[col], by = bias_s[col + 1];
                int r0 = nb0 + wr * 32 + mt * 16 + gidq;
                if (r0 < n) {
                    float2 o; o.x = acc[mt][nt][0] + bx; o.y = acc[mt][nt][1] + by;
                    *(float2*)(g_y + (size_t)r0 * 128 + col) = o;
                }
                if (r0 + 8 < n) {
                    float2 o; o.x = acc[mt][nt][2] + bx; o.y = acc[mt][nt][3] + by;
                    *(float2*)(g_y + (size_t)(r0 + 8) * 128 + col) = o;
                }
            }
        }
        __syncthreads();   // done reading As before next tile overwrites
    }
}

// ===========================================================================
// edge-side kernels (unchanged from best-passing R5)
// ===========================================================================
__global__ void zero_cnt_kernel(int n) {
    int i = blockIdx.x * blockDim.x + threadIdx.x;
    if (i < n) g_cnt[i] = 0;
}

__global__ void hist_kernel(const int* __restrict__ ei, int e, int n) {
    int t = blockIdx.x * blockDim.x + threadIdx.x;
    int base = t * 4;
    if (base + 4 <= e) {
        int4 d4 = *(const int4*)(ei + e + base);
        if ((unsigned)d4.x < (unsigned)n) atomicAdd(&g_cnt[d4.x], 1);
        if ((unsigned)d4.y < (unsigned)n) atomicAdd(&g_cnt[d4.y], 1);
        if ((unsigned)d4.z < (unsigned)n) atomicAdd(&g_cnt[d4.z], 1);
        if ((unsigned)d4.w < (unsigned)n) atomicAdd(&g_cnt[d4.w], 1);
    } else {
        for (int i = base; i < e; i++) {
            int dn = ei[e + i];
            if ((unsigned)dn < (unsigned)n) atomicAdd(&g_cnt[dn], 1);
        }
    }
}

__global__ void scan1_kernel(int n) {
    __shared__ int wsum[32];
    int tid = threadIdx.x, lane = tid & 31, wid = tid >> 5;
    int i = blockIdx.x * 1024 + tid;
    int v = (i < n) ? g_cnt[i] : 0;
    int inc = v;
#pragma unroll
    for (int off = 1; off < 32; off <<= 1) {
        int t = __shfl_up_sync(0xffffffffu, inc, off);
        if (lane >= off) inc += t;
    }
    if (lane == 31) wsum[wid] = inc;
    __syncthreads();
    if (wid == 0) {
        int s = wsum[lane];
#pragma unroll
        for (int off = 1; off < 32; off <<= 1) {
            int t = __shfl_up_sync(0xffffffffu, s, off);
            if (lane >= off) s += t;
        }
        wsum[lane] = s;
    }
    __syncthreads();
    int woff = (wid > 0) ? wsum[wid - 1] : 0;
    if (i < n) g_start[i] = woff + inc - v;
    if (tid == 1023) g_bsum[blockIdx.x] = wsum[31];
}

__global__ void scan2_kernel(int nb) {
    __shared__ int ws[8];
    int tid = threadIdx.x, lane = tid & 31, wid = tid >> 5;
    int v = (tid < nb) ? g_bsum[tid] : 0;
    int inc = v;
#pragma unroll
    for (int off = 1; off < 32; off <<= 1) {
        int t = __shfl_up_sync(0xffffffffu, inc, off);
        if (lane >= off) inc += t;
    }
    if (lane == 31) ws[wid] = inc;
    __syncthreads();
    if (wid == 0) {
        int s = (lane < 8) ? ws[lane] : 0;
#pragma unroll
        for (int off = 1; off < 8; off <<= 1) {
            int t = __shfl_up_sync(0xffffffffu, s, off);
            if (lane >= off) s += t;
        }
        if (lane < 8) ws[lane] = s;
    }
    __syncthreads();
    int woff = (wid > 0) ? ws[wid - 1] : 0;
    if (tid < nb) g_bsum[tid] = woff + inc - v;
}

__global__ void scan3_kernel(int n) {
    int i = blockIdx.x * blockDim.x + threadIdx.x;
    if (i < n) {
        int v = g_start[i] + g_bsum[i >> 10];
        g_start[i]  = v;
        g_cursor[i] = v;
    }
}

__global__ void place_kernel(const int* __restrict__ ei,
                             const int* __restrict__ attr, int e, int n) {
    int t = blockIdx.x * blockDim.x + threadIdx.x;
    int base = t * 4;
    if (base + 4 <= e) {
        int4 s4 = *(const int4*)(ei + base);
        int4 d4 = *(const int4*)(ei + e + base);
        int4 a4 = *(const int4*)(attr + base);
        int ss[4] = {s4.x, s4.y, s4.z, s4.w};
        int dd[4] = {d4.x, d4.y, d4.z, d4.w};
        int aa[4] = {a4.x, a4.y, a4.z, a4.w};
#pragma unroll
        for (int q = 0; q < 4; q++) {
            if ((unsigned)ss[q] < (unsigned)n && (unsigned)dd[q] < (unsigned)n) {
                int pos = atomicAdd(&g_cursor[dd[q]], 1);
                if ((unsigned)pos < (unsigned)MAXE)
                    g_edata[pos] = (unsigned)((ss[q] << 1) | (aa[q] & 1));
            }
        }
    } else {
        for (int i = base; i < e; i++) {
            int s = ei[i], dn = ei[e + i], a = attr[i] & 1;
            if ((unsigned)s < (unsigned)n && (unsigned)dn < (unsigned)n) {
                int pos = atomicAdd(&g_cursor[dn], 1);
                if ((unsigned)pos < (unsigned)MAXE)
                    g_edata[pos] = (unsigned)((s << 1) | a);
            }
        }
    }
}

// aggregation: warp/node, lane owns dims {2l,2l+1}; g_y row for packed idx u
// lives at g_y + u*64 (== node*128 + t*64).
__global__ void agg_kernel(float* __restrict__ out, int n) {
    int gt   = blockIdx.x * blockDim.x + threadIdx.x;
    int node = gt >> 5;
    int lane = gt & 31;
    if (node >= n) return;

    int c = g_cnt[node];
    int s = g_start[node];

    float vx = -CUDART_INF_F, vy = -CUDART_INF_F;
    for (int base = 0; base < c; base += 32) {
        int m = min(32, c - base);
        unsigned u = (lane < m) ? g_edata[s + base + lane] : 0u;
        int j = 0;
        for (; j + 4 <= m; j += 4) {
            unsigned u0 = __shfl_sync(0xffffffffu, u, j);
            unsigned u1 = __shfl_sync(0xffffffffu, u, j + 1);
            unsigned u2 = __shfl_sync(0xffffffffu, u, j + 2);
            unsigned u3 = __shfl_sync(0xffffffffu, u, j + 3);
            float2 v0 = ((const float2*)(g_y + (size_t)u0 * D))[lane];
            float2 v1 = ((const float2*)(g_y + (size_t)u1 * D))[lane];
            float2 v2 = ((const float2*)(g_y + (size_t)u2 * D))[lane];
            float2 v3 = ((const float2*)(g_y + (size_t)u3 * D))[lane];
            vx = fmaxf(vx, fmaxf(fmaxf(v0.x, v1.x), fmaxf(v2.x, v3.x)));
            vy = fmaxf(vy, fmaxf(fmaxf(v0.y, v1.y), fmaxf(v2.y, v3.y)));
        }
        for (; j < m; j++) {
            unsigned uu = __shfl_sync(0xffffffffu, u, j);
            float2 v = ((const float2*)(g_y + (size_t)uu * D))[lane];
            vx = fmaxf(vx, v.x);
            vy = fmaxf(vy, v.y);
        }
    }
    if (c == 0) { vx = 0.f; vy = 0.f; }
    float2 o; o.x = vx; o.y = vy;
    ((float2*)out)[(size_t)node * 32 + lane] = o;
}

// ---------------------------------------------------------------------------
extern "C" void kernel_launch(void* const* d_in, const int* in_sizes, int n_in,
                              void* d_out, int out_size) {
    const float* x    = (const float*)d_in[0];
    const float* W    = (const float*)d_in[1];
    const float* b    = (const float*)d_in[2];
    const int*   ei   = (const int*)d_in[3];
    const int*   attr = (const int*)d_in[4];
    float*       out  = (float*)d_out;

    int n = in_sizes[0] / D;
    int e = in_sizes[4];
    if (n > MAXN) n = MAXN;
    if (e > MAXE) e = MAXE;

    int et = (e + 3) / 4;
    int nb = (n + 1023) / 1024;

    cudaFuncSetAttribute(gemm_tc_kernel,
                         cudaFuncAttributeMaxDynamicSharedMemorySize, SMEM_BYTES);

    // gemm kept at launch slot 4 (the position ncu captures)
    zero_cnt_kernel<<<(n + 255) / 256, 256>>>(n);             // 1
    hist_kernel<<<(et + 255) / 256, 256>>>(ei, e, n);         // 2
    scan1_kernel<<<nb, 1024>>>(n);                            // 3
    gemm_tc_kernel<<<296, 256, SMEM_BYTES>>>(x, W, b, n);     // 4  <- profiled
    scan2_kernel<<<1, 256>>>(nb);                             // 5
    scan3_kernel<<<(n + 255) / 256, 256>>>(n);                // 6
    place_kernel<<<(et + 255) / 256, 256>>>(ei, attr, e, n);  // 7
    agg_kernel<<<(n * 32 + 255) / 256, 256>>>(out, n);        // 8
}

// round 8
// speedup vs baseline: 1.6869x; 1.0224x over previous
#include <cuda_runtime.h>
#include <math_constants.h>
#include <cstdint>

#define MAXN 100000
#define MAXE 1200000
#define D    64

__device__ float    g_y[(size_t)MAXN * 2 * D];   // y[node*128 + j], j = t*64+d
__device__ int      g_cnt[MAXN];
__device__ int      g_start[MAXN + 1];           // CSR offsets + total sentinel
__device__ int      g_cursor[MAXN];
__device__ unsigned g_edata[MAXE];               // packed (src*2 + type)
__device__ int      g_bsum[256];

// ---------------------------------------------------------------------------
// mma.sync tf32 helpers (portable PTX; sm_103a-gated instrs don't compile here)
// ---------------------------------------------------------------------------
__device__ __forceinline__ float to_tf32(float f) {
    uint32_t r;
    asm("cvt.rna.tf32.f32 %0, %1;" : "=r"(r) : "f"(f));
    return __uint_as_float(r);
}
__device__ __forceinline__ void mma8(float* c,
                                     float a0, float a1, float a2, float a3,
                                     float b0, float b1) {
    asm volatile(
        "mma.sync.aligned.m16n8k8.row.col.f32.tf32.tf32.f32 "
        "{%0,%1,%2,%3}, {%4,%5,%6,%7}, {%8,%9}, {%0,%1,%2,%3};"
        : "+f"(c[0]), "+f"(c[1]), "+f"(c[2]), "+f"(c[3])
        : "r"(__float_as_uint(a0)), "r"(__float_as_uint(a1)),
          "r"(__float_as_uint(a2)), "r"(__float_as_uint(a3)),
          "r"(__float_as_uint(b0)), "r"(__float_as_uint(b1)));
}

// XOR-swizzled float4 slot index: row stride 16 float4, slot j in [0,16)
#define ASW(row, j) (((row) << 4) + ((j) ^ (((row) & 3) << 2)))

// dynamic smem (float4 units): As 128*16, Bs 128*16, bias 128 floats
#define AS_OFF 0
#define BS_OFF (128 * 16)
#define BIAS_OFF (2 * 128 * 16)
#define SMEM_BYTES ((2 * 128 * 16) * 16 + 512)

// ---------------------------------------------------------------------------
// GEMM via mma.sync tf32: g_y[node][j] = x[node] @ W'[.][j] + b[j]
// 256 thr, tile 128x128, warp tile 32x64. K-pair packed slots: slot s2*4+t
// holds cols {16s2+t, +4, +8, +12}. XOR swizzle -> conflict-free LDS.128.
// ---------------------------------------------------------------------------
__global__ void __launch_bounds__(256, 2)
gemm_tc_kernel(const float* __restrict__ x,
               const float* __restrict__ W,
               const float* __restrict__ b, int n) {
    extern __shared__ float4 sm4[];
    float4* As = sm4 + AS_OFF;
    float4* Bs = sm4 + BS_OFF;
    float*  bias_s = (float*)(sm4 + BIAS_OFF);
    float*  Asf = (float*)As;

    const int tid  = threadIdx.x;
    const int wid  = tid >> 5, lane = tid & 31;
    const int gidq = lane >> 2, tq = lane & 3;
    const int wr   = wid >> 1,  wc = wid & 1;

    // stage W' once (tf32-rounded, K-pair packed, swizzled)
    for (int i = tid; i < 128 * 16; i += 256) {
        int nn = i >> 4, j = i & 15;
        int s2 = j >> 2, t = j & 3;
        const float* wp = W + ((nn >> 6) << 12) + (nn & 63);
        float4 v;
        v.x = to_tf32(wp[(16 * s2 + t     ) << 6]);
        v.y = to_tf32(wp[(16 * s2 + t + 4 ) << 6]);
        v.z = to_tf32(wp[(16 * s2 + t + 8 ) << 6]);
        v.w = to_tf32(wp[(16 * s2 + t + 12) << 6]);
        Bs[ASW(nn, j)] = v;
    }
    if (tid < 128) bias_s[tid] = b[tid];
    __syncthreads();

    const int ntiles = (n + 127) >> 7;
    for (int tile = blockIdx.x; tile < ntiles; tile += gridDim.x) {
        const int nb0 = tile << 7;

        // stage A tile: coalesced LDG.128, scatter into packed swizzled slots
#pragma unroll
        for (int s = 0; s < 8; s++) {
            int idx = s * 256 + tid;               // 2048 float4
            int row = idx >> 4, q = idx & 15;
            int gn = nb0 + row;
            float4 v = make_float4(0.f, 0.f, 0.f, 0.f);
            if (gn < n) v = *(const float4*)(x + (size_t)gn * 64 + q * 4);
            int s2 = q >> 2, p = q & 3;
            Asf[ASW(row, s2 * 4 + 0) * 4 + p] = to_tf32(v.x);
            Asf[ASW(row, s2 * 4 + 1) * 4 + p] = to_tf32(v.y);
            Asf[ASW(row, s2 * 4 + 2) * 4 + p] = to_tf32(v.z);
            Asf[ASW(row, s2 * 4 + 3) * 4 + p] = to_tf32(v.w);
        }
        __syncthreads();

        float acc[2][8][4];
#pragma unroll
        for (int mt = 0; mt < 2; mt++)
#pragma unroll
            for (int nt = 0; nt < 8; nt++)
#pragma unroll
                for (int c = 0; c < 4; c++) acc[mt][nt][c] = 0.f;

#pragma unroll
        for (int s2 = 0; s2 < 4; s2++) {
            float4 A0[2], A1[2];
#pragma unroll
            for (int mt = 0; mt < 2; mt++) {
                int r0 = wr * 32 + mt * 16 + gidq;
                A0[mt] = As[ASW(r0,     s2 * 4 + tq)];
                A1[mt] = As[ASW(r0 + 8, s2 * 4 + tq)];
            }
#pragma unroll
            for (int nt = 0; nt < 8; nt++) {
                int nn = wc * 64 + nt * 8 + gidq;
                float4 Bv = Bs[ASW(nn, s2 * 4 + tq)];
#pragma unroll
                for (int mt = 0; mt < 2; mt++) {
                    mma8(acc[mt][nt], A0[mt].x, A1[mt].x, A0[mt].y, A1[mt].y,
                         Bv.x, Bv.y);
                    mma8(acc[mt][nt], A0[mt].z, A1[mt].z, A0[mt].w, A1[mt].w,
                         Bv.z, Bv.w);
                }
            }
        }

        // epilogue: add bias, store float2 pairs
#pragma unroll
        for (int mt = 0; mt < 2; mt++) {
#pragma unroll
            for (int nt = 0; nt < 8; nt++) {
                int col = wc * 64 + nt * 8 + 2 * tq;
                float bx = bias_s[col], by = bias_s[col + 1];
                int r0 = nb0 + wr * 32 + mt * 16 + gidq;
                if (r0 < n) {
                    float2 o; o.x = acc[mt][nt][0] + bx; o.y = acc[mt][nt][1] + by;
                    *(float2*)(g_y + (size_t)r0 * 128 + col) = o;
                }
                if (r0 + 8 < n) {
                    float2 o; o.x = acc[mt][nt][2] + bx; o.y = acc[mt][nt][3] + by;
                    *(float2*)(g_y + (size_t)(r0 + 8) * 128 + col) = o;
                }
            }
        }
        __syncthreads();
    }
}

// ===========================================================================
// edge-side kernels
// ===========================================================================
__global__ void hist_kernel(const int* __restrict__ ei, int e, int n) {
    int t = blockIdx.x * blockDim.x + threadIdx.x;
    int base = t * 4;
    if (base + 4 <= e) {
        int4 d4 = *(const int4*)(ei + e + base);
        if ((unsigned)d4.x < (unsigned)n) atomicAdd(&g_cnt[d4.x], 1);
        if ((unsigned)d4.y < (unsigned)n) atomicAdd(&g_cnt[d4.y], 1);
        if ((unsigned)d4.z < (unsigned)n) atomicAdd(&g_cnt[d4.z], 1);
        if ((unsigned)d4.w < (unsigned)n) atomicAdd(&g_cnt[d4.w], 1);
    } else {
        for (int i = base; i < e; i++) {
            int dn = ei[e + i];
            if ((unsigned)dn < (unsigned)n) atomicAdd(&g_cnt[dn], 1);
        }
    }
}

__global__ void scan1_kernel(int n) {
    __shared__ int wsum[32];
    int tid = threadIdx.x, lane = tid & 31, wid = tid >> 5;
    int i = blockIdx.x * 1024 + tid;
    int v = (i < n) ? g_cnt[i] : 0;
    int inc = v;
#pragma unroll
    for (int off = 1; off < 32; off <<= 1) {
        int t = __shfl_up_sync(0xffffffffu, inc, off);
        if (lane >= off) inc += t;
    }
    if (lane == 31) wsum[wid] = inc;
    __syncthreads();
    if (wid == 0) {
        int s = wsum[lane];
#pragma unroll
        for (int off = 1; off < 32; off <<= 1) {
            int t = __shfl_up_sync(0xffffffffu, s, off);
            if (lane >= off) s += t;
        }
        wsum[lane] = s;
    }
    __syncthreads();
    int woff = (wid > 0) ? wsum[wid - 1] : 0;
    if (i < n) g_start[i] = woff + inc - v;
    if (tid == 1023) g_bsum[blockIdx.x] = wsum[31];
}

// scan3 with scan2 folded in: one warp computes the bsum prefix for this
// block's 1024-segment (nb <= 128), all threads then add it.
__global__ void scan3_kernel(int n, int nb) {
    __shared__ int s_pref, s_tot;
    int tid = threadIdx.x;
    int seg = blockIdx.x >> 2;               // 256-thread block within one segment
    if (tid < 32) {
        int acc = 0, tot = 0;
        for (int j = tid; j < nb; j += 32) {
            int v = g_bsum[j];
            tot += v;
            if (j < seg) acc += v;
        }
#pragma unroll
        for (int o = 16; o; o >>= 1) {
            acc += __shfl_down_sync(0xffffffffu, acc, o);
            tot += __shfl_down_sync(0xffffffffu, tot, o);
        }
        if (tid == 0) { s_pref = acc; s_tot = tot; }
    }
    __syncthreads();
    int i = blockIdx.x * 256 + tid;
    if (i < n) {
        int v = g_start[i] + s_pref;
        g_start[i]  = v;
        g_cursor[i] = v;
    }
    if (i == n - 1) g_start[n] = s_tot;      // sentinel: total edge count
}

__global__ void place_kernel(const int* __restrict__ ei,
                             const int* __restrict__ attr, int e, int n) {
    int t = blockIdx.x * blockDim.x + threadIdx.x;
    int base = t * 4;
    if (base + 4 <= e) {
        int4 s4 = *(const int4*)(ei + base);
        int4 d4 = *(const int4*)(ei + e + base);
        int4 a4 = *(const int4*)(attr + base);
        int ss[4] = {s4.x, s4.y, s4.z, s4.w};
        int dd[4] = {d4.x, d4.y, d4.z, d4.w};
        int aa[4] = {a4.x, a4.y, a4.z, a4.w};
#pragma unroll
        for (int q = 0; q < 4; q++) {
            if ((unsigned)ss[q] < (unsigned)n && (unsigned)dd[q] < (unsigned)n) {
                int pos = atomicAdd(&g_cursor[dd[q]], 1);
                if ((unsigned)pos < (unsigned)MAXE)
                    g_edata[pos] = (unsigned)((ss[q] << 1) | (aa[q] & 1));
            }
        }
    } else {
        for (int i = base; i < e; i++) {
            int s = ei[i], dn = ei[e + i], a = attr[i] & 1;
            if ((unsigned)s < (unsigned)n && (unsigned)dn < (unsigned)n) {
                int pos = atomicAdd(&g_cursor[dn], 1);
                if ((unsigned)pos < (unsigned)MAXE)
                    g_edata[pos] = (unsigned)((s << 1) | a);
            }
        }
    }
}

// aggregation: warp/node, lane owns dims {2l,2l+1}; degree from g_start diff.
// Also resets g_cnt for the next graph replay (hist is the next consumer).
__global__ void agg_kernel(float* __restrict__ out, int n) {
    int gt   = blockIdx.x * blockDim.x + threadIdx.x;
    int node = gt >> 5;
    int lane = gt & 31;
    if (node >= n) return;

    int s = g_start[node];
    int c = g_start[node + 1] - s;
    g_cnt[node] = 0;                       // reset histogram for next replay

    float vx = -CUDART_INF_F, vy = -CUDART_INF_F;
    for (int base = 0; base < c; base += 32) {
        int m = min(32, c - base);
        unsigned u = (lane < m) ? g_edata[s + base + lane] : 0u;
        int j = 0;
        for (; j + 8 <= m; j += 8) {
            unsigned q0 = __shfl_sync(0xffffffffu, u, j);
            unsigned q1 = __shfl_sync(0xffffffffu, u, j + 1);
            unsigned q2 = __shfl_sync(0xffffffffu, u, j + 2);
            unsigned q3 = __shfl_sync(0xffffffffu, u, j + 3);
            unsigned q4 = __shfl_sync(0xffffffffu, u, j + 4);
            unsigned q5 = __shfl_sync(0xffffffffu, u, j + 5);
            unsigned q6 = __shfl_sync(0xffffffffu, u, j + 6);
            unsigned q7 = __shfl_sync(0xffffffffu, u, j + 7);
            float2 v0 = ((const float2*)(g_y + (size_t)q0 * D))[lane];
            float2 v1 = ((const float2*)(g_y + (size_t)q1 * D))[lane];
            float2 v2 = ((const float2*)(g_y + (size_t)q2 * D))[lane];
            float2 v3 = ((const float2*)(g_y + (size_t)q3 * D))[lane];
            float2 v4 = ((const float2*)(g_y + (size_t)q4 * D))[lane];
            float2 v5 = ((const float2*)(g_y + (size_t)q5 * D))[lane];
            float2 v6 = ((const float2*)(g_y + (size_t)q6 * D))[lane];
            float2 v7 = ((const float2*)(g_y + (size_t)q7 * D))[lane];
            vx = fmaxf(vx, fmaxf(fmaxf(fmaxf(v0.x, v1.x), fmaxf(v2.x, v3.x)),
                                 fmaxf(fmaxf(v4.x, v5.x), fmaxf(v6.x, v7.x))));
            vy = fmaxf(vy, fmaxf(fmaxf(fmaxf(v0.y, v1.y), fmaxf(v2.y, v3.y)),
                                 fmaxf(fmaxf(v4.y, v5.y), fmaxf(v6.y, v7.y))));
        }
        for (; j + 4 <= m; j += 4) {
            unsigned q0 = __shfl_sync(0xffffffffu, u, j);
            unsigned q1 = __shfl_sync(0xffffffffu, u, j + 1);
            unsigned q2 = __shfl_sync(0xffffffffu, u, j + 2);
            unsigned q3 = __shfl_sync(0xffffffffu, u, j + 3);
            float2 v0 = ((const float2*)(g_y + (size_t)q0 * D))[lane];
            float2 v1 = ((const float2*)(g_y + (size_t)q1 * D))[lane];
            float2 v2 = ((const float2*)(g_y + (size_t)q2 * D))[lane];
            float2 v3 = ((const float2*)(g_y + (size_t)q3 * D))[lane];
            vx = fmaxf(vx, fmaxf(fmaxf(v0.x, v1.x), fmaxf(v2.x, v3.x)));
            vy = fmaxf(vy, fmaxf(fmaxf(v0.y, v1.y), fmaxf(v2.y, v3.y)));
        }
        for (; j < m; j++) {
            unsigned qq = __shfl_sync(0xffffffffu, u, j);
            float2 v = ((const float2*)(g_y + (size_t)qq * D))[lane];
            vx = fmaxf(vx, v.x);
            vy = fmaxf(vy, v.y);
        }
    }
    if (c == 0) { vx = 0.f; vy = 0.f; }
    float2 o; o.x = vx; o.y = vy;
    ((float2*)out)[(size_t)node * 32 + lane] = o;
}

// ---------------------------------------------------------------------------
extern "C" void kernel_launch(void* const* d_in, const int* in_sizes, int n_in,
                              void* d_out, int out_size) {
    const float* x    = (const float*)d_in[0];
    const float* W    = (const float*)d_in[1];
    const float* b    = (const float*)d_in[2];
    const int*   ei   = (const int*)d_in[3];
    const int*   attr = (const int*)d_in[4];
    float*       out  = (float*)d_out;

    int n = in_sizes[0] / D;
    int e = in_sizes[4];
    if (n > MAXN) n = MAXN;
    if (e > MAXE) e = MAXE;

    int et = (e + 3) / 4;
    int nb = (n + 1023) / 1024;

    cudaFuncSetAttribute(gemm_tc_kernel,
                         cudaFuncAttributeMaxDynamicSharedMemorySize, SMEM_BYTES);

    // g_cnt zeroed by previous replay's agg (and by static init on first run).
    // gemm stays at launch slot 4 (the position ncu captures).
    hist_kernel<<<(et + 255) / 256, 256>>>(ei, e, n);         // 1
    scan1_kernel<<<nb, 1024>>>(n);                            // 2
    scan3_kernel<<<(n + 255) / 256, 256>>>(n, nb);            // 3
    gemm_tc_kernel<<<296, 256, SMEM_BYTES>>>(x, W, b, n);     // 4  <- profiled
    place_kernel<<<(et + 255) / 256, 256>>>(ei, attr, e, n);  // 5
    agg_kernel<<<(n * 32 + 255) / 256, 256>>>(out, n);        // 6
}

// round 10
// speedup vs baseline: 1.9027x; 1.1279x over previous
#include <cuda_runtime.h>
#include <math_constants.h>
#include <cstdint>

#define MAXN 100000
#define MAXE 1200000
#define D    64
#define GGRID 296     // gemm blocks inside the fused kernel

__device__ float    g_y[(size_t)MAXN * 2 * D];   // y[node*128 + j], j = t*64+d
__device__ int      g_cnt[MAXN];
__device__ int      g_start[MAXN + 1];           // CSR offsets + total sentinel
__device__ int      g_cursor[MAXN];
__device__ unsigned g_edata[MAXE];               // packed (src*2 + type)
__device__ volatile unsigned long long g_stat[128];  // lookback: flag<<62|pref<<24|agg

// ---------------------------------------------------------------------------
// mma.sync tf32 helpers (portable PTX; sm_103a-gated instrs don't compile here)
// ---------------------------------------------------------------------------
__device__ __forceinline__ float to_tf32(float f) {
    uint32_t r;
    asm("cvt.rna.tf32.f32 %0, %1;" : "=r"(r) : "f"(f));
    return __uint_as_float(r);
}
__device__ __forceinline__ void mma8(float* c,
                                     float a0, float a1, float a2, float a3,
                                     float b0, float b1) {
    asm volatile(
        "mma.sync.aligned.m16n8k8.row.col.f32.tf32.tf32.f32 "
        "{%0,%1,%2,%3}, {%4,%5,%6,%7}, {%8,%9}, {%0,%1,%2,%3};"
        : "+f"(c[0]), "+f"(c[1]), "+f"(c[2]), "+f"(c[3])
        : "r"(__float_as_uint(a0)), "r"(__float_as_uint(a1)),
          "r"(__float_as_uint(a2)), "r"(__float_as_uint(a3)),
          "r"(__float_as_uint(b0)), "r"(__float_as_uint(b1)));
}

#define ASW(row, j) (((row) << 4) + ((j) ^ (((row) & 3) << 2)))
#define AS_OFF 0
#define BS_OFF (128 * 16)
#define BIAS_OFF (2 * 128 * 16)
#define SMEM_BYTES ((2 * 128 * 16) * 16 + 512)

// ---------------------------------------------------------------------------
// K1: fused  [blocks 0..GGRID)  tf32 GEMM   |   [GGRID..) dst histogram
// ---------------------------------------------------------------------------
__global__ void __launch_bounds__(256, 2)
fused_gemm_hist(const float* __restrict__ x,
                const float* __restrict__ W,
                const float* __restrict__ b,
                const int* __restrict__ ei, int n, int e) {
    const int tid = threadIdx.x;

    if ((int)blockIdx.x >= GGRID) {
        // ---- histogram path ----
        int hb = blockIdx.x - GGRID;
        if (hb == 0 && tid < 128) g_stat[tid] = 0;   // reset lookback state
        int t = hb * 256 + tid;
        int base = t * 4;
        if (base + 4 <= e) {
            int4 d4 = *(const int4*)(ei + e + base);
            if ((unsigned)d4.x < (unsigned)n) atomicAdd(&g_cnt[d4.x], 1);
            if ((unsigned)d4.y < (unsigned)n) atomicAdd(&g_cnt[d4.y], 1);
            if ((unsigned)d4.z < (unsigned)n) atomicAdd(&g_cnt[d4.z], 1);
            if ((unsigned)d4.w < (unsigned)n) atomicAdd(&g_cnt[d4.w], 1);
        } else {
            for (int i = base; i < e; i++) {
                int dn = ei[e + i];
                if ((unsigned)dn < (unsigned)n) atomicAdd(&g_cnt[dn], 1);
            }
        }
        return;
    }

    // ---- gemm path ----
    extern __shared__ float4 sm4[];
    float4* As = sm4 + AS_OFF;
    float4* Bs = sm4 + BS_OFF;
    float*  bias_s = (float*)(sm4 + BIAS_OFF);
    float*  Asf = (float*)As;

    const int wid  = tid >> 5, lane = tid & 31;
    const int gidq = lane >> 2, tq = lane & 3;
    const int wr   = wid >> 1,  wc = wid & 1;

    for (int i = tid; i < 128 * 16; i += 256) {
        int nn = i >> 4, j = i & 15;
        int s2 = j >> 2, t = j & 3;
        const float* wp = W + ((nn >> 6) << 12) + (nn & 63);
        float4 v;
        v.x = to_tf32(wp[(16 * s2 + t     ) << 6]);
        v.y = to_tf32(wp[(16 * s2 + t + 4 ) << 6]);
        v.z = to_tf32(wp[(16 * s2 + t + 8 ) << 6]);
        v.w = to_tf32(wp[(16 * s2 + t + 12) << 6]);
        Bs[ASW(nn, j)] = v;
    }
    if (tid < 128) bias_s[tid] = b[tid];
    __syncthreads();

    const int ntiles = (n + 127) >> 7;
    for (int tile = blockIdx.x; tile < ntiles; tile += GGRID) {
        const int nb0 = tile << 7;

#pragma unroll
        for (int s = 0; s < 8; s++) {
            int idx = s * 256 + tid;
            int row = idx >> 4, q = idx & 15;
            int gn = nb0 + row;
            float4 v = make_float4(0.f, 0.f, 0.f, 0.f);
            if (gn < n) v = *(const float4*)(x + (size_t)gn * 64 + q * 4);
            int s2 = q >> 2, p = q & 3;
            Asf[ASW(row, s2 * 4 + 0) * 4 + p] = to_tf32(v.x);
            Asf[ASW(row, s2 * 4 + 1) * 4 + p] = to_tf32(v.y);
            Asf[ASW(row, s2 * 4 + 2) * 4 + p] = to_tf32(v.z);
            Asf[ASW(row, s2 * 4 + 3) * 4 + p] = to_tf32(v.w);
        }
        __syncthreads();

        float acc[2][8][4];
#pragma unroll
        for (int mt = 0; mt < 2; mt++)
#pragma unroll
            for (int nt = 0; nt < 8; nt++)
#pragma unroll
                for (int c = 0; c < 4; c++) acc[mt][nt][c] = 0.f;

#pragma unroll
        for (int s2 = 0; s2 < 4; s2++) {
            float4 A0[2], A1[2];
#pragma unroll
            for (int mt = 0; mt < 2; mt++) {
                int r0 = wr * 32 + mt * 16 + gidq;
                A0[mt] = As[ASW(r0,     s2 * 4 + tq)];
                A1[mt] = As[ASW(r0 + 8, s2 * 4 + tq)];
            }
#pragma unroll
            for (int nt = 0; nt < 8; nt++) {
                int nn = wc * 64 + nt * 8 + gidq;
                float4 Bv = Bs[ASW(nn, s2 * 4 + tq)];
#pragma unroll
                for (int mt = 0; mt < 2; mt++) {
                    mma8(acc[mt][nt], A0[mt].x, A1[mt].x, A0[mt].y, A1[mt].y,
                         Bv.x, Bv.y);
                    mma8(acc[mt][nt], A0[mt].z, A1[mt].z, A0[mt].w, A1[mt].w,
                         Bv.z, Bv.w);
                }
            }
        }

#pragma unroll
        for (int mt = 0; mt < 2; mt++) {
#pragma unroll
            for (int nt = 0; nt < 8; nt++) {
                int col = wc * 64 + nt * 8 + 2 * tq;
                float bx = bias_s[col], by = bias_s[col + 1];
                int r0 = nb0 + wr * 32 + mt * 16 + gidq;
                if (r0 < n) {
                    float2 o; o.x = acc[mt][nt][0] + bx; o.y = acc[mt][nt][1] + by;
                    *(float2*)(g_y + (size_t)r0 * 128 + col) = o;
                }
                if (r0 + 8 < n) {
                    float2 o; o.x = acc[mt][nt][2] + bx; o.y = acc[mt][nt][3] + by;
                    *(float2*)(g_y + (size_t)(r0 + 8) * 128 + col) = o;
                }
            }
        }
        __syncthreads();
    }
}

// ---------------------------------------------------------------------------
// K2: single-pass exclusive scan, warp-parallel decoupled lookback.
// stat word: flag(2b)<<62 | inclusive_prefix<<24 | aggregate  (values < 2^24)
// ---------------------------------------------------------------------------
__global__ void scan_kernel(int n) {
    __shared__ int wsum[32];
    __shared__ int s_prefix;
    int tid = threadIdx.x, lane = tid & 31, wid = tid >> 5;
    int b = blockIdx.x;
    int i = b * 1024 + tid;
    int v = (i < n) ? g_cnt[i] : 0;
    int inc = v;
#pragma unroll
    for (int off = 1; off < 32; off <<= 1) {
        int t = __shfl_up_sync(0xffffffffu, inc, off);
        if (lane >= off) inc += t;
    }
    if (lane == 31) wsum[wid] = inc;
    __syncthreads();
    if (wid == 0) {
        int s = wsum[lane];
#pragma unroll
        for (int off = 1; off < 32; off <<= 1) {
            int t = __shfl_up_sync(0xffffffffu, s, off);
            if (lane >= off) s += t;
        }
        wsum[lane] = s;
        int total = __shfl_sync(0xffffffffu, s, 31);
        if (lane == 0)
            atomicExch((unsigned long long*)&g_stat[b],
                       (1ULL << 62) | (unsigned long long)(unsigned)total);
        int pref = 0;
        int end = b;
        while (end > 0) {
            int j = end - 32 + lane;
            unsigned fl = 2, ag = 0, pr = 0;
            if (j >= 0) {
                unsigned long long s64;
                do { s64 = g_stat[j]; fl = (unsigned)(s64 >> 62); } while (fl == 0);
                ag = (unsigned)(s64 & 0xFFFFFFu);
                pr = (unsigned)((s64 >> 24) & 0xFFFFFFu);
            }
            unsigned pm = __ballot_sync(0xffffffffu, fl == 2);
            if (pm) {
                int hp = 31 - __clz(pm);
                int contrib = (lane > hp) ? (int)ag : ((lane == hp) ? (int)pr : 0);
                pref += __reduce_add_sync(0xffffffffu, contrib);
                break;
            } else {
                pref += __reduce_add_sync(0xffffffffu, (int)ag);
                end -= 32;
            }
        }
        if (lane == 0) {
            atomicExch((unsigned long long*)&g_stat[b],
                (2ULL << 62) |
                ((unsigned long long)(unsigned)(pref + total) << 24) |
                (unsigned long long)(unsigned)total);
            s_prefix = pref;
        }
    }
    __syncthreads();
    int woff = (wid > 0) ? wsum[wid - 1] : 0;
    int p = s_prefix;
    if (i < n) {
        int vv = p + woff + inc - v;
        g_start[i]  = vv;
        g_cursor[i] = vv;
        if (i == n - 1) g_start[n] = p + woff + inc;   // total sentinel
    }
}

// ---------------------------------------------------------------------------
// K3: placement, 4 edges/thread
// ---------------------------------------------------------------------------
__global__ void place_kernel(const int* __restrict__ ei,
                             const int* __restrict__ attr, int e, int n) {
    int t = blockIdx.x * blockDim.x + threadIdx.x;
    int base = t * 4;
    if (base + 4 <= e) {
        int4 s4 = *(const int4*)(ei + base);
        int4 d4 = *(const int4*)(ei + e + base);
        int4 a4 = *(const int4*)(attr + base);
        int ss[4] = {s4.x, s4.y, s4.z, s4.w};
        int dd[4] = {d4.x, d4.y, d4.z, d4.w};
        int aa[4] = {a4.x, a4.y, a4.z, a4.w};
#pragma unroll
        for (int q = 0; q < 4; q++) {
            if ((unsigned)ss[q] < (unsigned)n && (unsigned)dd[q] < (unsigned)n) {
                int pos = atomicAdd(&g_cursor[dd[q]], 1);
                if ((unsigned)pos < (unsigned)MAXE)
                    g_edata[pos] = (unsigned)((ss[q] << 1) | (aa[q] & 1));
            }
        }
    } else {
        for (int i = base; i < e; i++) {
            int s = ei[i], dn = ei[e + i], a = attr[i] & 1;
            if ((unsigned)s < (unsigned)n && (unsigned)dn < (unsigned)n) {
                int pos = atomicAdd(&g_cursor[dn], 1);
                if ((unsigned)pos < (unsigned)MAXE)
                    g_edata[pos] = (unsigned)((s << 1) | a);
            }
        }
    }
}

// ---------------------------------------------------------------------------
// K4: aggregation — warp/node, lane owns dims {2l,2l+1}; unroll-8 gathers.
// Resets g_cnt for the next replay.
// ---------------------------------------------------------------------------
__global__ void agg_kernel(float* __restrict__ out, int n) {
    int gt   = blockIdx.x * blockDim.x + threadIdx.x;
    int node = gt >> 5;
    int lane = gt & 31;
    if (node >= n) return;

    int s = g_start[node];
    int c = g_start[node + 1] - s;
    g_cnt[node] = 0;

    float vx = -CUDART_INF_F, vy = -CUDART_INF_F;
    for (int base = 0; base < c; base += 32) {
        int m = min(32, c - base);
        unsigned u = (lane < m) ? g_edata[s + base + lane] : 0u;
        int j = 0;
        for (; j + 8 <= m; j += 8) {
            unsigned q0 = __shfl_sync(0xffffffffu, u, j);
            unsigned q1 = __shfl_sync(0xffffffffu, u, j + 1);
            unsigned q2 = __shfl_sync(0xffffffffu, u, j + 2);
            unsigned q3 = __shfl_sync(0xffffffffu, u, j + 3);
            unsigned q4 = __shfl_sync(0xffffffffu, u, j + 4);
            unsigned q5 = __shfl_sync(0xffffffffu, u, j + 5);
            unsigned q6 = __shfl_sync(0xffffffffu, u, j + 6);
            unsigned q7 = __shfl_sync(0xffffffffu, u, j + 7);
            float2 v0 = ((const float2*)(g_y + (size_t)q0 * D))[lane];
            float2 v1 = ((const float2*)(g_y + (size_t)q1 * D))[lane];
            float2 v2 = ((const float2*)(g_y + (size_t)q2 * D))[lane];
            float2 v3 = ((const float2*)(g_y + (size_t)q3 * D))[lane];
            float2 v4 = ((const float2*)(g_y + (size_t)q4 * D))[lane];
            float2 v5 = ((const float2*)(g_y + (size_t)q5 * D))[lane];
            float2 v6 = ((const float2*)(g_y + (size_t)q6 * D))[lane];
            float2 v7 = ((const float2*)(g_y + (size_t)q7 * D))[lane];
            vx = fmaxf(vx, fmaxf(fmaxf(fmaxf(v0.x, v1.x), fmaxf(v2.x, v3.x)),
                                 fmaxf(fmaxf(v4.x, v5.x), fmaxf(v6.x, v7.x))));
            vy = fmaxf(vy, fmaxf(fmaxf(fmaxf(v0.y, v1.y), fmaxf(v2.y, v3.y)),
                                 fmaxf(fmaxf(v4.y, v5.y), fmaxf(v6.y, v7.y))));
        }
        for (; j + 4 <= m; j += 4) {
            unsigned q0 = __shfl_sync(0xffffffffu, u, j);
            unsigned q1 = __shfl_sync(0xffffffffu, u, j + 1);
            unsigned q2 = __shfl_sync(0xffffffffu, u, j + 2);
            unsigned q3 = __shfl_sync(0xffffffffu, u, j + 3);
            float2 v0 = ((const float2*)(g_y + (size_t)q0 * D))[lane];
            float2 v1 = ((const float2*)(g_y + (size_t)q1 * D))[lane];
            float2 v2 = ((const float2*)(g_y + (size_t)q2 * D))[lane];
            float2 v3 = ((const float2*)(g_y + (size_t)q3 * D))[lane];
            vx = fmaxf(vx, fmaxf(fmaxf(v0.x, v1.x), fmaxf(v2.x, v3.x)));
            vy = fmaxf(vy, fmaxf(fmaxf(v0.y, v1.y), fmaxf(v2.y, v3.y)));
        }
        for (; j < m; j++) {
            unsigned qq = __shfl_sync(0xffffffffu, u, j);
            float2 v = ((const float2*)(g_y + (size_t)qq * D))[lane];
            vx = fmaxf(vx, v.x);
            vy = fmaxf(vy, v.y);
        }
    }
    if (c == 0) { vx = 0.f; vy = 0.f; }
    float2 o; o.x = vx; o.y = vy;
    ((float2*)out)[(size_t)node * 32 + lane] = o;
}

// ---------------------------------------------------------------------------
extern "C" void kernel_launch(void* const* d_in, const int* in_sizes, int n_in,
                              void* d_out, int out_size) {
    const float* x    = (const float*)d_in[0];
    const float* W    = (const float*)d_in[1];
    const float* b    = (const float*)d_in[2];
    const int*   ei   = (const int*)d_in[3];
    const int*   attr = (const int*)d_in[4];
    float*       out  = (float*)d_out;

    int n = in_sizes[0] / D;
    int e = in_sizes[4];
    if (n > MAXN) n = MAXN;
    if (e > MAXE) e = MAXE;

    int et = (e + 3) / 4;
    int hblocks = (et + 255) / 256;
    int nb = (n + 1023) / 1024;

    // 66 KB dynamic smem needs the opt-in (this was the R9 failure).
    static int smem_attr_set = 0;
    if (!smem_attr_set) {
        cudaFuncSetAttribute(fused_gemm_hist,
                             cudaFuncAttributeMaxDynamicSharedMemorySize,
                             SMEM_BYTES);
        smem_attr_set = 1;
    }

    // 4 launches; slot 4 (= ncu capture position) is the aggregation kernel.
    fused_gemm_hist<<<GGRID + hblocks, 256, SMEM_BYTES>>>(x, W, b, ei, n, e); // 1
    scan_kernel<<<nb, 1024>>>(n);                                             // 2
    place_kernel<<<(et + 255) / 256, 256>>>(ei, attr, e, n);                  // 3
    agg_kernel<<<(n * 32 + 255) / 256, 256>>>(out, n);                        // 4 <- profiled
}